// round 1
// baseline (speedup 1.0000x reference)
#include <cuda_runtime.h>

typedef unsigned long long ull;
typedef unsigned int uint_;

#define B_   8
#define C_   256
#define H_   128
#define W_   128
#define CR_  32
#define HW_  (H_ * W_)

// ---------------- scratch (device globals; no runtime allocation) -------------
__device__ float g_q [B_ * CR_ * HW_];   // (b, cr, h, w)
__device__ float g_k [B_ * CR_ * HW_];
__device__ float g_v [B_ * CR_ * HW_];
__device__ float g_qt[B_ * CR_ * HW_];   // (b, cr, w, h)
__device__ float g_kt[B_ * CR_ * HW_];
__device__ float g_vt[B_ * CR_ * HW_];
__device__ float g_oH[B_ * CR_ * HW_];   // (b, cr, w, h)  unnormalized H-path out
__device__ float g_oW[B_ * CR_ * HW_];   // (b, cr, h, w)  unnormalized W-path out
__device__ float g_mH[B_ * HW_];         // (b, h, w)
__device__ float g_sH[B_ * HW_];
__device__ float g_mW[B_ * HW_];
__device__ float g_sW[B_ * HW_];

// ---------------- packed f32x2 helpers ---------------------------------------
__device__ __forceinline__ ull fma2(ull a, ull b, ull c) {
    ull d;
    asm("fma.rn.f32x2 %0, %1, %2, %3;" : "=l"(d) : "l"(a), "l"(b), "l"(c));
    return d;
}
__device__ __forceinline__ ull splat2(float f) {
    ull r; uint_ u = __float_as_uint(f);
    asm("mov.b64 %0, {%1, %1};" : "=l"(r) : "r"(u));
    return r;
}
__device__ __forceinline__ ull pack2(float lo, float hi) {
    ull r;
    asm("mov.b64 %0, {%1, %2};" : "=l"(r)
        : "r"(__float_as_uint(lo)), "r"(__float_as_uint(hi)));
    return r;
}
__device__ __forceinline__ float2 unpack2(ull u) {
    uint_ lo, hi;
    asm("mov.b64 {%0, %1}, %2;" : "=r"(lo), "=r"(hi) : "l"(u));
    return make_float2(__uint_as_float(lo), __uint_as_float(hi));
}
__device__ __forceinline__ ull ldpair(const float* p) {
    union { float2 f2; ull u; } t;
    t.f2 = *reinterpret_cast<const float2*>(p);
    return t.u;
}

// ---------------- kernel 1: fused q/k/v projection ----------------------------
// grid (H, B), 256 threads. Block computes 96 out-channels x 128 w for one (b,h).
__global__ void __launch_bounds__(256) proj_kernel(
    const float* __restrict__ x,
    const float* __restrict__ Wq, const float* __restrict__ bq,
    const float* __restrict__ Wk, const float* __restrict__ bk,
    const float* __restrict__ Wv, const float* __restrict__ bv)
{
    __shared__ float xs[32 * 128];   // 32 channels x 128 w chunk
    __shared__ float ws[96 * 32];    // 96 out rows x 32 channel chunk

    int h = blockIdx.x, b = blockIdx.y;
    int tid = threadIdx.x;
    int ty = tid >> 5, tx = tid & 31;

    const float* xb = x + (size_t)b * C_ * HW_ + (size_t)h * W_;

    ull acc[12][2];
#pragma unroll
    for (int j = 0; j < 12; j++) { acc[j][0] = 0ull; acc[j][1] = 0ull; }

    for (int kc = 0; kc < 8; kc++) {
#pragma unroll
        for (int idx = tid; idx < 32 * 128; idx += 256) {
            int cc = idx >> 7, w = idx & 127;
            xs[idx] = xb[(size_t)(kc * 32 + cc) * HW_ + w];
        }
#pragma unroll
        for (int idx = tid; idx < 96 * 32; idx += 256) {
            int r = idx >> 5, cc = idx & 31;
            float wv;
            if (r < 32)      wv = Wq[r * C_ + kc * 32 + cc];
            else if (r < 64) wv = Wk[(r - 32) * C_ + kc * 32 + cc];
            else             wv = Wv[(r - 64) * C_ + kc * 32 + cc];
            ws[idx] = wv;
        }
        __syncthreads();

#pragma unroll 4
        for (int c = 0; c < 32; c++) {
            ull x0 = ldpair(&xs[c * 128 + 2 * tx]);
            ull x1 = ldpair(&xs[c * 128 + 2 * tx + 64]);
#pragma unroll
            for (int j = 0; j < 12; j++) {
                ull wv = splat2(ws[(ty + 8 * j) * 32 + c]);
                acc[j][0] = fma2(wv, x0, acc[j][0]);
                acc[j][1] = fma2(wv, x1, acc[j][1]);
            }
        }
        __syncthreads();
    }

#pragma unroll
    for (int j = 0; j < 12; j++) {
        int r = ty + 8 * j;
        float bias; float* dst;
        if (r < 32)      { bias = bq[r];      dst = g_q + ((size_t)(b * CR_ + r)      * H_ + h) * W_; }
        else if (r < 64) { bias = bk[r - 32]; dst = g_k + ((size_t)(b * CR_ + r - 32) * H_ + h) * W_; }
        else             { bias = bv[r - 64]; dst = g_v + ((size_t)(b * CR_ + r - 64) * H_ + h) * W_; }
#pragma unroll
        for (int u = 0; u < 2; u++) {
            float2 v = unpack2(acc[j][u]);
            v.x += bias; v.y += bias;
            *reinterpret_cast<float2*>(&dst[2 * tx + 64 * u]) = v;
        }
    }
}

// ---------------- kernel 2: HxW transpose of q/k/v ----------------------------
// grid (4, 4, 3*B*CR), block (32, 8)
__global__ void __launch_bounds__(256) transpose_kernel()
{
    __shared__ float tile[32][33];
    int zc = blockIdx.z;
    int arr = zc >> 8, m = zc & 255;
    const float* src = (arr == 0 ? g_q  : arr == 1 ? g_k  : g_v ) + (size_t)m * HW_;
    float*       dst = (arr == 0 ? g_qt : arr == 1 ? g_kt : g_vt) + (size_t)m * HW_;
    int x0 = blockIdx.x * 32, y0 = blockIdx.y * 32;
    int tx = threadIdx.x, ty = threadIdx.y;
#pragma unroll
    for (int r = 0; r < 32; r += 8)
        tile[ty + r][tx] = src[(size_t)(y0 + ty + r) * W_ + x0 + tx];
    __syncthreads();
#pragma unroll
    for (int r = 0; r < 32; r += 8)
        dst[(size_t)(x0 + ty + r) * H_ + y0 + tx] = tile[tx][ty + r];
}

// ---------------- kernel 3: attention path (gram -> softmax -> P.V) ----------
// grid (128, B), 256 threads, dynamic smem.
// transposed=1: H path on qt/kt/vt  (X=w, row=h, mask diag, stats at (b,row,X))
// transposed=0: W path on q/k/v    (X=h, row=w, no mask,   stats at (b,X,row))
#define ATTN_SMEM ((32 * 130 * 2 + 128 * 33 + 128 * 128) * 4)

__global__ void __launch_bounds__(256) attn_kernel(int transposed)
{
    extern __shared__ float sm[];
    float* Qs  = sm;                        // 32 x 130 (padded)
    float* Ks  = sm + 32 * 130;             // 32 x 130
    float* Vst = sm + 64 * 130;             // 128 x 33  (transposed V: [i][c])
    float* E   = sm + 64 * 130 + 128 * 33;  // 128 x 128 (energies -> probs)

    const float* qin = transposed ? g_qt : g_q;
    const float* kin = transposed ? g_kt : g_k;
    const float* vin = transposed ? g_vt : g_v;
    float* outp  = transposed ? g_oH : g_oW;
    float* mstat = transposed ? g_mH : g_mW;
    float* sstat = transposed ? g_sH : g_sW;

    int X = blockIdx.x, b = blockIdx.y;
    size_t base = (size_t)b * CR_ * HW_ + (size_t)X * W_;
    int tid = threadIdx.x, warp = tid >> 5, lane = tid & 31;

    for (int idx = tid; idx < CR_ * 128; idx += 256) {
        int c = idx >> 7, e = idx & 127;
        Qs[c * 130 + e] = qin[base + (size_t)c * HW_ + e];
        Ks[c * 130 + e] = kin[base + (size_t)c * HW_ + e];
        Vst[e * 33 + c] = vin[base + (size_t)c * HW_ + e];
    }
    __syncthreads();

    // gram: E[r][i] = sum_c Q[c][r] * K[c][i]; warp owns 16 rows, lane owns i pairs
    ull acc[16][2];
#pragma unroll
    for (int t = 0; t < 16; t++) { acc[t][0] = 0ull; acc[t][1] = 0ull; }

#pragma unroll 4
    for (int c = 0; c < 32; c++) {
        ull k0 = ldpair(&Ks[c * 130 + 2 * lane]);
        ull k1 = ldpair(&Ks[c * 130 + 2 * lane + 64]);
#pragma unroll
        for (int t = 0; t < 16; t++) {
            ull qv = splat2(Qs[c * 130 + warp * 16 + t]);
            acc[t][0] = fma2(qv, k0, acc[t][0]);
            acc[t][1] = fma2(qv, k1, acc[t][1]);
        }
    }

    // per-row softmax (local max/sum); write probs back to E, stats to gmem
#pragma unroll
    for (int t = 0; t < 16; t++) {
        int r = warp * 16 + t;
        float2 a0 = unpack2(acc[t][0]);
        float2 a1 = unpack2(acc[t][1]);
        if (transposed) {
            int i0 = 2 * lane;
            if (i0      == r) a0.x = -1e30f;
            if (i0 + 1  == r) a0.y = -1e30f;
            if (i0 + 64 == r) a1.x = -1e30f;
            if (i0 + 65 == r) a1.y = -1e30f;
        }
        float mx = fmaxf(fmaxf(a0.x, a0.y), fmaxf(a1.x, a1.y));
#pragma unroll
        for (int o = 16; o > 0; o >>= 1) mx = fmaxf(mx, __shfl_xor_sync(0xffffffffu, mx, o));
        float p0 = __expf(a0.x - mx), p1 = __expf(a0.y - mx);
        float p2 = __expf(a1.x - mx), p3 = __expf(a1.y - mx);
        float sum = (p0 + p1) + (p2 + p3);
#pragma unroll
        for (int o = 16; o > 0; o >>= 1) sum += __shfl_xor_sync(0xffffffffu, sum, o);
        *reinterpret_cast<float2*>(&E[r * 128 + 2 * lane])      = make_float2(p0, p1);
        *reinterpret_cast<float2*>(&E[r * 128 + 2 * lane + 64]) = make_float2(p2, p3);
        if (lane == 0) {
            size_t sidx = transposed ? ((size_t)(b * H_ + r) * W_ + X)
                                     : ((size_t)(b * H_ + X) * W_ + r);
            mstat[sidx] = mx;
            sstat[sidx] = sum;
        }
    }
    __syncthreads();

    // aggregation: out[c=lane][r] = sum_i V[i][c] * P[r][i]
    ull agg[16];
#pragma unroll
    for (int t = 0; t < 16; t++) agg[t] = 0ull;

    for (int i = 0; i < 128; i += 2) {
        ull vv = pack2(Vst[i * 33 + lane], Vst[(i + 1) * 33 + lane]);
#pragma unroll
        for (int t = 0; t < 16; t++) {
            ull pp = ldpair(&E[(warp * 16 + t) * 128 + i]);
            agg[t] = fma2(pp, vv, agg[t]);
        }
    }

    // stage transposed into smem (reuse Qs) so global writes are coalesced
#pragma unroll
    for (int t = 0; t < 16; t++) {
        float2 s = unpack2(agg[t]);
        Qs[lane * 130 + warp * 16 + t] = s.x + s.y;
    }
    __syncthreads();
    for (int idx = tid; idx < CR_ * 128; idx += 256) {
        int c = idx >> 7, e = idx & 127;
        outp[base + (size_t)c * HW_ + e] = Qs[c * 130 + e];
    }
}

// ---------------- kernel 4: softmax merge + Wz conv + bias + residual --------
// grid (H, B), 512 threads, dynamic smem
#define COMB_SMEM ((32 * 130 + 256 * 32 + 256) * 4)

__global__ void __launch_bounds__(512) combine_kernel(
    const float* __restrict__ x, const float* __restrict__ Wz,
    const float* __restrict__ bz, float* __restrict__ out)
{
    extern __shared__ float sm[];
    float* mg  = sm;                     // 32 x 130 merged attention output
    float* Wzs = sm + 32 * 130;          // 256 x 32
    float* fH  = sm + 32 * 130 + 256 * 32;  // 128
    float* fW  = fH + 128;                  // 128

    int h = blockIdx.x, b = blockIdx.y;
    int tid = threadIdx.x, wp = tid >> 5, lane = tid & 31;

    if (tid < 128) {
        int w = tid;
        size_t sidx = (size_t)(b * H_ + h) * W_ + w;
        float mh = g_mH[sidx], mw = g_mW[sidx];
        float sh = g_sH[sidx], sw = g_sW[sidx];
        float m  = fmaxf(mh, mw);
        float eh = __expf(mh - m), ew = __expf(mw - m);
        float inv = 1.0f / (sh * eh + sw * ew);
        fH[w] = eh * inv;
        fW[w] = ew * inv;
    }
    for (int idx = tid; idx < 256 * 32; idx += 512)
        Wzs[idx] = Wz[idx];
    __syncthreads();

    for (int idx = tid; idx < 32 * 128; idx += 512) {
        int c = idx >> 7, w = idx & 127;
        float oW = g_oW[(size_t)(b * CR_ + c) * HW_ + (size_t)h * W_ + w];
        float oH = g_oH[(size_t)(b * CR_ + c) * HW_ + (size_t)w * H_ + h];
        mg[c * 130 + w] = oH * fH[w] + oW * fW[w];
    }
    __syncthreads();

    // z[o][w] = sum_c Wz[o][c] * mg[c][w]; 16 warps x 16 o-rows, lane owns w pairs
    ull acc[16][2];
#pragma unroll
    for (int j = 0; j < 16; j++) { acc[j][0] = 0ull; acc[j][1] = 0ull; }

#pragma unroll 4
    for (int c = 0; c < 32; c++) {
        ull m0 = ldpair(&mg[c * 130 + 2 * lane]);
        ull m1 = ldpair(&mg[c * 130 + 2 * lane + 64]);
#pragma unroll
        for (int j = 0; j < 16; j++) {
            ull wv = splat2(Wzs[(wp + 16 * j) * 32 + c]);
            acc[j][0] = fma2(wv, m0, acc[j][0]);
            acc[j][1] = fma2(wv, m1, acc[j][1]);
        }
    }

#pragma unroll
    for (int j = 0; j < 16; j++) {
        int o = wp + 16 * j;
        float bias = bz[o];
        size_t obase = ((size_t)(b * C_ + o) * H_ + h) * W_;
#pragma unroll
        for (int u = 0; u < 2; u++) {
            int w = 2 * lane + 64 * u;
            float2 xv = *reinterpret_cast<const float2*>(&x[obase + w]);
            float2 a  = unpack2(acc[j][u]);
            a.x += bias + xv.x;
            a.y += bias + xv.y;
            *reinterpret_cast<float2*>(&out[obase + w]) = a;
        }
    }
}

// ---------------- launch ------------------------------------------------------
extern "C" void kernel_launch(void* const* d_in, const int* in_sizes, int n_in,
                              void* d_out, int out_size)
{
    const float* x  = (const float*)d_in[0];
    const float* Wq = (const float*)d_in[1];
    const float* bq = (const float*)d_in[2];
    const float* Wk = (const float*)d_in[3];
    const float* bk = (const float*)d_in[4];
    const float* Wv = (const float*)d_in[5];
    const float* bv = (const float*)d_in[6];
    const float* Wz = (const float*)d_in[7];
    const float* bz = (const float*)d_in[8];
    float* out = (float*)d_out;

    cudaFuncSetAttribute(attn_kernel,    cudaFuncAttributeMaxDynamicSharedMemorySize, ATTN_SMEM);
    cudaFuncSetAttribute(combine_kernel, cudaFuncAttributeMaxDynamicSharedMemorySize, COMB_SMEM);

    proj_kernel<<<dim3(H_, B_), 256>>>(x, Wq, bq, Wk, bk, Wv, bv);
    transpose_kernel<<<dim3(4, 4, 3 * B_ * CR_), dim3(32, 8)>>>();
    attn_kernel<<<dim3(W_, B_), 256, ATTN_SMEM>>>(1);   // H path (transposed)
    attn_kernel<<<dim3(H_, B_), 256, ATTN_SMEM>>>(0);   // W path
    combine_kernel<<<dim3(H_, B_), 512, COMB_SMEM>>>(x, Wz, bz, out);
}